// round 1
// baseline (speedup 1.0000x reference)
#include <cuda_runtime.h>
#include <cstdint>

// Problem shape (fixed by the reference):
//   a: [M_TOTAL, K] f32, b: [G, K, N] f32, group_list: [G] i32 cumulative ends
//   out: [M_TOTAL * N] f32
static constexpr int M_TOTAL = 16384;
static constexpr int K = 512;
static constexpr int N = 512;
static constexpr int G = 8;

// Tiling
#define BM 128
#define BN 128
#define BK 16
#define TM 8
#define TN 8
#define NTHREADS 256

__global__ __launch_bounds__(NTHREADS)
void grouped_gemm_f32_kernel(const float* __restrict__ A,
                             const float* __restrict__ B,
                             const int*   __restrict__ glist,
                             float*       __restrict__ C) {
    __shared__ float As[BK][BM];   // A tile, transposed: As[k][m]
    __shared__ float Bs[BK][BN];   // B tile: Bs[k][n]

    const int bn = blockIdx.x;          // N tile
    const int bm = blockIdx.y;          // M tile
    const int row0 = bm * BM;
    const int col0 = bn * BN;
    const int tid = threadIdx.x;
    const int tx = tid & 15;            // 16 threads across N
    const int ty = tid >> 4;            // 16 threads across M

    // group_list into registers (G=8, tiny)
    int gl[G];
    #pragma unroll
    for (int g = 0; g < G; g++) gl[g] = glist[g];

    // gid(row) = first g with gl[g] > row  (searchsorted side='right')
    auto gid_of = [&](int row) {
        int g = 0;
        #pragma unroll
        for (int i = 0; i < G; i++) if (row >= gl[i]) g = i + 1;
        return g;
    };
    const int g0 = gid_of(row0);
    const int g1 = gid_of(row0 + BM - 1);
    const bool uniform = (g0 == g1);

    float acc[TM][TN];
    #pragma unroll
    for (int i = 0; i < TM; i++)
        #pragma unroll
        for (int j = 0; j < TN; j++) acc[i][j] = 0.0f;

    // Normally one iteration (tiles don't straddle groups for this layout);
    // straddling tiles are handled by masking A rows per group pass.
    for (int g = g0; g <= g1; ++g) {
        const int lo = (g == 0) ? 0 : gl[g - 1];
        const int hi = gl[g];
        const float* __restrict__ Bg = B + (size_t)g * K * N;

        for (int kt = 0; kt < K; kt += BK) {
            // ---- load A tile: BM x BK (512 float4 loads, 2 per thread) ----
            #pragma unroll
            for (int i = 0; i < 2; i++) {
                const int idx = tid + i * NTHREADS;     // 0..511
                const int r  = idx >> 2;                // row in tile (0..127)
                const int kq = (idx & 3) * 4;           // k offset (0,4,8,12)
                const int grow = row0 + r;
                float4 v;
                if (uniform || (grow >= lo && grow < hi)) {
                    v = *reinterpret_cast<const float4*>(
                        &A[(size_t)grow * K + kt + kq]);
                } else {
                    v = make_float4(0.f, 0.f, 0.f, 0.f);
                }
                As[kq + 0][r] = v.x;
                As[kq + 1][r] = v.y;
                As[kq + 2][r] = v.z;
                As[kq + 3][r] = v.w;
            }
            // ---- load B tile: BK x BN (512 float4 loads, 2 per thread) ----
            #pragma unroll
            for (int i = 0; i < 2; i++) {
                const int idx = tid + i * NTHREADS;     // 0..511
                const int r  = idx >> 5;                // k row (0..15)
                const int nq = (idx & 31) * 4;          // n offset
                *reinterpret_cast<float4*>(&Bs[r][nq]) =
                    *reinterpret_cast<const float4*>(
                        &Bg[(size_t)(kt + r) * N + col0 + nq]);
            }
            __syncthreads();

            // ---- compute 8x8 micro-tile over BK ----
            #pragma unroll
            for (int k = 0; k < BK; k++) {
                float a[TM], b[TN];
                #pragma unroll
                for (int i = 0; i < TM; i++) a[i] = As[k][ty * TM + i];
                #pragma unroll
                for (int j = 0; j < TN; j++) b[j] = Bs[k][tx * TN + j];
                #pragma unroll
                for (int i = 0; i < TM; i++)
                    #pragma unroll
                    for (int j = 0; j < TN; j++)
                        acc[i][j] = fmaf(a[i], b[j], acc[i][j]);
            }
            __syncthreads();
        }
    }

    // ---- epilogue: vectorized stores ----
    #pragma unroll
    for (int i = 0; i < TM; i++) {
        const int r = row0 + ty * TM + i;
        #pragma unroll
        for (int j = 0; j < TN; j += 4) {
            float4 v = make_float4(acc[i][j], acc[i][j + 1],
                                   acc[i][j + 2], acc[i][j + 3]);
            *reinterpret_cast<float4*>(
                &C[(size_t)r * N + col0 + tx * TN + j]) = v;
        }
    }
}

extern "C" void kernel_launch(void* const* d_in, const int* in_sizes, int n_in,
                              void* d_out, int out_size) {
    const float* a     = (const float*)d_in[0];   // [M_TOTAL, K]
    const float* b     = (const float*)d_in[1];   // [G, K, N]
    const int*   gls   = (const int*)d_in[2];     // [G]
    float*       out   = (float*)d_out;           // [M_TOTAL * N]

    dim3 grid(N / BN, M_TOTAL / BM);              // (4, 128)
    dim3 block(NTHREADS);
    grouped_gemm_f32_kernel<<<grid, block>>>(a, b, gls, out);
}

// round 6
// speedup vs baseline: 2.2398x; 2.2398x over previous
#include <cuda_runtime.h>
#include <cuda_bf16.h>
#include <cstdint>

static constexpr int M_TOTAL = 16384;
static constexpr int K = 512;
static constexpr int N = 512;
static constexpr int G = 8;

#define BM 128
#define BN 128
#define KC 64               // K chunk: 64 bf16 = 128 bytes/row (SW128 atom)
#define NTHREADS 256

// ---- B transposed + split scratch: Bt[g][n][k], hi and lo bf16 ----
__device__ __nv_bfloat16 g_Bth[(size_t)G * N * K];
__device__ __nv_bfloat16 g_Btl[(size_t)G * N * K];

// ============================ helpers ============================

__device__ __forceinline__ uint32_t smem_u32(const void* p) {
    uint32_t a;
    asm("{ .reg .u64 t; cvta.to.shared.u64 t, %1; cvt.u32.u64 %0, t; }"
        : "=r"(a) : "l"(p));
    return a;
}

__device__ __forceinline__ void ldsm_x4(uint32_t* r, uint32_t addr) {
    asm volatile("ldmatrix.sync.aligned.m8n8.x4.shared.b16 {%0,%1,%2,%3}, [%4];"
                 : "=r"(r[0]), "=r"(r[1]), "=r"(r[2]), "=r"(r[3]) : "r"(addr));
}
__device__ __forceinline__ void ldsm_x2(uint32_t* r, uint32_t addr) {
    asm volatile("ldmatrix.sync.aligned.m8n8.x2.shared.b16 {%0,%1}, [%2];"
                 : "=r"(r[0]), "=r"(r[1]) : "r"(addr));
}

__device__ __forceinline__ void mma16816(float* d, const uint32_t* a, const uint32_t* b) {
    asm volatile(
        "mma.sync.aligned.m16n8k16.row.col.f32.bf16.bf16.f32 "
        "{%0,%1,%2,%3}, {%4,%5,%6,%7}, {%8,%9}, {%0,%1,%2,%3};"
        : "+f"(d[0]), "+f"(d[1]), "+f"(d[2]), "+f"(d[3])
        : "r"(a[0]), "r"(a[1]), "r"(a[2]), "r"(a[3]), "r"(b[0]), "r"(b[1]));
}

__device__ __forceinline__ uint32_t swz128(uint32_t b) {
    return b ^ ((b >> 3) & 0x70);
}

// ============================ kernel 1: B transpose + bf16 split ============================

__global__ __launch_bounds__(256)
void b_transpose_split(const float* __restrict__ B) {
    __shared__ float t[32][33];
    const int g  = blockIdx.z;
    const int k0 = blockIdx.y * 32;
    const int n0 = blockIdx.x * 32;
    const int x = threadIdx.x;        // 0..31
    const int y = threadIdx.y;        // 0..7
    const float* Bg = B + (size_t)g * K * N;
    #pragma unroll
    for (int i = 0; i < 4; i++)
        t[y + 8 * i][x] = Bg[(size_t)(k0 + y + 8 * i) * N + n0 + x];
    __syncthreads();
    #pragma unroll
    for (int i = 0; i < 4; i++) {
        const int n = n0 + y + 8 * i;
        const int k = k0 + x;
        float v = t[x][y + 8 * i];
        __nv_bfloat16 hi = __float2bfloat16(v);
        __nv_bfloat16 lo = __float2bfloat16(v - __bfloat162float(hi));
        const size_t o = ((size_t)g * N + n) * K + k;
        g_Bth[o] = hi;
        g_Btl[o] = lo;
    }
}

// ============================ kernel 2: grouped GEMM via mma.sync bf16x3 ============================

// dynamic SMEM (from 1024-aligned base): 4 tiles of [128 rows x 128 bytes], SW128-swizzled
static constexpr int OFF_AH = 0;
static constexpr int OFF_AL = 16384;
static constexpr int OFF_BH = 2 * 16384;
static constexpr int OFF_BL = 3 * 16384;
static constexpr int SMEM_BYTES = 1024 /*align slack*/ + 4 * 16384;

__global__ __launch_bounds__(NTHREADS, 1)
void grouped_gemm_mma_kernel(const float* __restrict__ A,
                             const int*   __restrict__ glist,
                             float*       __restrict__ C) {
    extern __shared__ char dynsmem[];
    const uint32_t raw   = smem_u32(dynsmem);
    const uint32_t sbase = (raw + 1023u) & ~1023u;
    char* sptr = dynsmem + (sbase - raw);

    const int tid  = threadIdx.x;
    const int wid  = tid >> 5;
    const int lane = tid & 31;
    const int warp_m = wid >> 1;            // 0..3 -> 32-row slab
    const int warp_n = wid & 1;             // 0..1 -> 64-col slab
    const int row0 = blockIdx.y * BM;
    const int col0 = blockIdx.x * BN;

    // group bounds
    int gl[G];
    #pragma unroll
    for (int g = 0; g < G; g++) gl[g] = glist[g];
    auto gid_of = [&](int row) {
        int g = 0;
        #pragma unroll
        for (int i = 0; i < G; i++) if (row >= gl[i]) g = i + 1;
        return g;
    };
    const int g0 = gid_of(row0);
    const int g1 = gid_of(row0 + BM - 1);

    float acc[2][8][4];
    #pragma unroll
    for (int mt = 0; mt < 2; mt++)
        #pragma unroll
        for (int nt = 0; nt < 8; nt++)
            #pragma unroll
            for (int i = 0; i < 4; i++) acc[mt][nt][i] = 0.0f;

    // per-lane ldmatrix addressing components
    const int laneA_r = lane & 15;                  // row within 16-row A tile
    const int laneA_c = (lane >> 4) << 4;           // 0 or 16 bytes (k8 select)
    const int laneB_r = lane & 7;                   // row within 8-row B tile
    const int laneB_c = ((lane >> 3) & 1) << 4;     // 0 or 16 bytes

    for (int g = g0; g <= g1; ++g) {
        const int glo = (g == 0) ? 0 : gl[g - 1];
        const int ghi = gl[g];
        const __nv_bfloat16* __restrict__ Bh = g_Bth + ((size_t)g * N + col0) * K;
        const __nv_bfloat16* __restrict__ Bl = g_Btl + ((size_t)g * N + col0) * K;

        for (int kt = 0; kt < K; kt += KC) {
            // ---- A chunk: 128 rows x 64 k fp32 -> hi/lo bf16, swizzled SMEM ----
            #pragma unroll
            for (int i = 0; i < 8; i++) {
                const int idx = tid + i * NTHREADS;   // 0..2047 (float4 units)
                const int r = idx >> 4;               // row 0..127
                const int q = (idx & 15) * 4;         // k offset 0..60
                const int grow = row0 + r;
                float4 v = make_float4(0.f, 0.f, 0.f, 0.f);
                if (grow >= glo && grow < ghi)
                    v = *reinterpret_cast<const float4*>(&A[(size_t)grow * K + kt + q]);
                __nv_bfloat16 hx = __float2bfloat16(v.x);
                __nv_bfloat16 hy = __float2bfloat16(v.y);
                __nv_bfloat16 hz = __float2bfloat16(v.z);
                __nv_bfloat16 hw = __float2bfloat16(v.w);
                __nv_bfloat16 lx = __float2bfloat16(v.x - __bfloat162float(hx));
                __nv_bfloat16 ly = __float2bfloat16(v.y - __bfloat162float(hy));
                __nv_bfloat16 lz = __float2bfloat16(v.z - __bfloat162float(hz));
                __nv_bfloat16 lw = __float2bfloat16(v.w - __bfloat162float(hw));
                uint32_t h01, h23, l01, l23;
                asm("mov.b32 %0, {%1, %2};" : "=r"(h01) : "h"(__nv_bfloat16_raw(hx).x), "h"(__nv_bfloat16_raw(hy).x));
                asm("mov.b32 %0, {%1, %2};" : "=r"(h23) : "h"(__nv_bfloat16_raw(hz).x), "h"(__nv_bfloat16_raw(hw).x));
                asm("mov.b32 %0, {%1, %2};" : "=r"(l01) : "h"(__nv_bfloat16_raw(lx).x), "h"(__nv_bfloat16_raw(ly).x));
                asm("mov.b32 %0, {%1, %2};" : "=r"(l23) : "h"(__nv_bfloat16_raw(lz).x), "h"(__nv_bfloat16_raw(lw).x));
                const uint32_t b0 = (uint32_t)(r * 128 + q * 2);
                *reinterpret_cast<uint32_t*>(sptr + OFF_AH + swz128(b0))     = h01;
                *reinterpret_cast<uint32_t*>(sptr + OFF_AH + swz128(b0 + 4)) = h23;
                *reinterpret_cast<uint32_t*>(sptr + OFF_AL + swz128(b0))     = l01;
                *reinterpret_cast<uint32_t*>(sptr + OFF_AL + swz128(b0 + 4)) = l23;
            }
            // ---- B chunk: 128 n-rows x 64 k bf16 (hi/lo), swizzled SMEM ----
            #pragma unroll
            for (int i = 0; i < 4; i++) {
                const int idx = tid + i * NTHREADS;   // 0..1023 (uint4 units)
                const int r = idx >> 3;               // n-row 0..127
                const int q = idx & 7;                // 16B chunk 0..7
                const uint32_t b0 = swz128((uint32_t)(r * 128 + q * 16));
                *reinterpret_cast<uint4*>(sptr + OFF_BH + b0) =
                    *reinterpret_cast<const uint4*>(
                        reinterpret_cast<const char*>(Bh + (size_t)r * K + kt) + q * 16);
                *reinterpret_cast<uint4*>(sptr + OFF_BL + b0) =
                    *reinterpret_cast<const uint4*>(
                        reinterpret_cast<const char*>(Bl + (size_t)r * K + kt) + q * 16);
            }
            __syncthreads();

            // ---- compute: 4 k16 sub-tiles, 3 bf16 products each ----
            #pragma unroll
            for (int ks = 0; ks < 4; ks++) {
                const int ca = ks * 32;   // byte offset of this k16 tile within row

                uint32_t ah[2][4], al[2][4], bh[8][2], bl[8][2];
                #pragma unroll
                for (int mt = 0; mt < 2; mt++) {
                    const int r = warp_m * 32 + mt * 16 + laneA_r;
                    const uint32_t c = (uint32_t)(ca + laneA_c) ^ (uint32_t)((r & 7) << 4);
                    ldsm_x4(ah[mt], sbase + OFF_AH + r * 128 + c);
                }
                #pragma unroll
                for (int nt = 0; nt < 8; nt++) {
                    const int r = warp_n * 64 + nt * 8 + laneB_r;
                    const uint32_t c = (uint32_t)(ca + laneB_c) ^ (uint32_t)((r & 7) << 4);
                    ldsm_x2(bh[nt], sbase + OFF_BH + r * 128 + c);
                }
                #pragma unroll
                for (int mt = 0; mt < 2; mt++)
                    #pragma unroll
                    for (int nt = 0; nt < 8; nt++)
                        mma16816(acc[mt][nt], ah[mt], bh[nt]);

                #pragma unroll
                for (int nt = 0; nt < 8; nt++) {
                    const int r = warp_n * 64 + nt * 8 + laneB_r;
                    const uint32_t c = (uint32_t)(ca + laneB_c) ^ (uint32_t)((r & 7) << 4);
                    ldsm_x2(bl[nt], sbase + OFF_BL + r * 128 + c);
                }
                #pragma unroll
                for (int mt = 0; mt < 2; mt++)
                    #pragma unroll
                    for (int nt = 0; nt < 8; nt++)
                        mma16816(acc[mt][nt], ah[mt], bl[nt]);

                #pragma unroll
                for (int mt = 0; mt < 2; mt++) {
                    const int r = warp_m * 32 + mt * 16 + laneA_r;
                    const uint32_t c = (uint32_t)(ca + laneA_c) ^ (uint32_t)((r & 7) << 4);
                    ldsm_x4(al[mt], sbase + OFF_AL + r * 128 + c);
                }
                #pragma unroll
                for (int mt = 0; mt < 2; mt++)
                    #pragma unroll
                    for (int nt = 0; nt < 8; nt++)
                        mma16816(acc[mt][nt], al[mt], bh[nt]);
            }
            __syncthreads();
        }
    }

    // ---- epilogue: direct coalesced stores (full 32B sectors per row-group) ----
    const int rbase = row0 + warp_m * 32 + (lane >> 2);
    const int cbase = col0 + warp_n * 64 + 2 * (lane & 3);
    #pragma unroll
    for (int mt = 0; mt < 2; mt++) {
        #pragma unroll
        for (int nt = 0; nt < 8; nt++) {
            const int r = rbase + mt * 16;
            const int c = cbase + nt * 8;
            *reinterpret_cast<float2*>(&C[(size_t)r * N + c]) =
                make_float2(acc[mt][nt][0], acc[mt][nt][1]);
            *reinterpret_cast<float2*>(&C[(size_t)(r + 8) * N + c]) =
                make_float2(acc[mt][nt][2], acc[mt][nt][3]);
        }
    }
}

// ============================ launch ============================

extern "C" void kernel_launch(void* const* d_in, const int* in_sizes, int n_in,
                              void* d_out, int out_size) {
    const float* a   = (const float*)d_in[0];   // [M_TOTAL, K]
    const float* b   = (const float*)d_in[1];   // [G, K, N]
    const int*   gls = (const int*)d_in[2];     // [G]
    float*       out = (float*)d_out;           // [M_TOTAL * N]

    // 1) transpose + split B into bf16 hi/lo scratch
    {
        dim3 grid(N / 32, K / 32, G);
        dim3 block(32, 8);
        b_transpose_split<<<grid, block>>>(b);
    }
    // 2) grouped GEMM on HMMA (mma.sync bf16x3)
    {
        cudaFuncSetAttribute(grouped_gemm_mma_kernel,
                             cudaFuncAttributeMaxDynamicSharedMemorySize, SMEM_BYTES);
        dim3 grid(N / BN, M_TOTAL / BM);   // (4, 128)
        grouped_gemm_mma_kernel<<<grid, NTHREADS, SMEM_BYTES>>>(a, gls, out);
    }
}

// round 7
// speedup vs baseline: 2.5799x; 1.1519x over previous
#include <cuda_runtime.h>
#include <cuda_bf16.h>
#include <cstdint>

static constexpr int M_TOTAL = 16384;
static constexpr int K = 512;
static constexpr int N = 512;
static constexpr int G = 8;

#define BM 128
#define BN 128
#define KC 64               // K chunk: 64 bf16 = 128 bytes/row (SW128 atom)
#define NTHREADS 256

// ---- pre-split scratch ----
// A split: Ath/Atl [M][K] bf16 (row-major, same layout as A)
__device__ __nv_bfloat16 g_Ath[(size_t)M_TOTAL * K];
__device__ __nv_bfloat16 g_Atl[(size_t)M_TOTAL * K];
// B transposed + split: Bt[g][n][k] bf16
__device__ __nv_bfloat16 g_Bth[(size_t)G * N * K];
__device__ __nv_bfloat16 g_Btl[(size_t)G * N * K];

// ============================ helpers ============================

__device__ __forceinline__ uint32_t smem_u32(const void* p) {
    uint32_t a;
    asm("{ .reg .u64 t; cvta.to.shared.u64 t, %1; cvt.u32.u64 %0, t; }"
        : "=r"(a) : "l"(p));
    return a;
}

__device__ __forceinline__ void ldsm_x4(uint32_t* r, uint32_t addr) {
    asm volatile("ldmatrix.sync.aligned.m8n8.x4.shared.b16 {%0,%1,%2,%3}, [%4];"
                 : "=r"(r[0]), "=r"(r[1]), "=r"(r[2]), "=r"(r[3]) : "r"(addr));
}
__device__ __forceinline__ void ldsm_x2(uint32_t* r, uint32_t addr) {
    asm volatile("ldmatrix.sync.aligned.m8n8.x2.shared.b16 {%0,%1}, [%2];"
                 : "=r"(r[0]), "=r"(r[1]) : "r"(addr));
}

__device__ __forceinline__ void mma16816(float* d, const uint32_t* a, const uint32_t* b) {
    asm volatile(
        "mma.sync.aligned.m16n8k16.row.col.f32.bf16.bf16.f32 "
        "{%0,%1,%2,%3}, {%4,%5,%6,%7}, {%8,%9}, {%0,%1,%2,%3};"
        : "+f"(d[0]), "+f"(d[1]), "+f"(d[2]), "+f"(d[3])
        : "r"(a[0]), "r"(a[1]), "r"(a[2]), "r"(a[3]), "r"(b[0]), "r"(b[1]));
}

__device__ __forceinline__ uint32_t swz128(uint32_t b) {
    return b ^ ((b >> 3) & 0x70);
}

// cp.async 16B with runtime src-size (0 => zero-fill)
__device__ __forceinline__ void cp16(uint32_t smem_dst, const void* gsrc, uint32_t srcbytes) {
    asm volatile("cp.async.cg.shared.global [%0], [%1], 16, %2;"
                 :: "r"(smem_dst), "l"(gsrc), "r"(srcbytes) : "memory");
}
__device__ __forceinline__ void cp16(uint32_t smem_dst, const void* gsrc) {
    asm volatile("cp.async.cg.shared.global [%0], [%1], 16;"
                 :: "r"(smem_dst), "l"(gsrc) : "memory");
}

// ============================ kernel 1a: A bf16 split ============================

__global__ __launch_bounds__(256)
void a_split(const float* __restrict__ A) {
    const size_t idx = (size_t)blockIdx.x * 256 + threadIdx.x;   // float4 index
    const float4 v = reinterpret_cast<const float4*>(A)[idx];
    __nv_bfloat16 hx = __float2bfloat16(v.x);
    __nv_bfloat16 hy = __float2bfloat16(v.y);
    __nv_bfloat16 hz = __float2bfloat16(v.z);
    __nv_bfloat16 hw = __float2bfloat16(v.w);
    __nv_bfloat16 lx = __float2bfloat16(v.x - __bfloat162float(hx));
    __nv_bfloat16 ly = __float2bfloat16(v.y - __bfloat162float(hy));
    __nv_bfloat16 lz = __float2bfloat16(v.z - __bfloat162float(hz));
    __nv_bfloat16 lw = __float2bfloat16(v.w - __bfloat162float(hw));
    uint32_t h01, h23, l01, l23;
    asm("mov.b32 %0, {%1, %2};" : "=r"(h01) : "h"(__nv_bfloat16_raw(hx).x), "h"(__nv_bfloat16_raw(hy).x));
    asm("mov.b32 %0, {%1, %2};" : "=r"(h23) : "h"(__nv_bfloat16_raw(hz).x), "h"(__nv_bfloat16_raw(hw).x));
    asm("mov.b32 %0, {%1, %2};" : "=r"(l01) : "h"(__nv_bfloat16_raw(lx).x), "h"(__nv_bfloat16_raw(ly).x));
    asm("mov.b32 %0, {%1, %2};" : "=r"(l23) : "h"(__nv_bfloat16_raw(lz).x), "h"(__nv_bfloat16_raw(lw).x));
    reinterpret_cast<uint2*>(g_Ath)[idx] = make_uint2(h01, h23);
    reinterpret_cast<uint2*>(g_Atl)[idx] = make_uint2(l01, l23);
}

// ============================ kernel 1b: B transpose + bf16 split ============================

__global__ __launch_bounds__(256)
void b_transpose_split(const float* __restrict__ B) {
    __shared__ float t[32][33];
    const int g  = blockIdx.z;
    const int k0 = blockIdx.y * 32;
    const int n0 = blockIdx.x * 32;
    const int x = threadIdx.x;        // 0..31
    const int y = threadIdx.y;        // 0..7
    const float* Bg = B + (size_t)g * K * N;
    #pragma unroll
    for (int i = 0; i < 4; i++)
        t[y + 8 * i][x] = Bg[(size_t)(k0 + y + 8 * i) * N + n0 + x];
    __syncthreads();
    #pragma unroll
    for (int i = 0; i < 4; i++) {
        const int n = n0 + y + 8 * i;
        const int k = k0 + x;
        float v = t[x][y + 8 * i];
        __nv_bfloat16 hi = __float2bfloat16(v);
        __nv_bfloat16 lo = __float2bfloat16(v - __bfloat162float(hi));
        const size_t o = ((size_t)g * N + n) * K + k;
        g_Bth[o] = hi;
        g_Btl[o] = lo;
    }
}

// ============================ kernel 2: pipelined grouped GEMM via mma.sync bf16x3 ============================

// dynamic SMEM: 2 stages x 4 tiles of [128 rows x 128 bytes], SW128-swizzled
static constexpr int OFF_AH = 0;
static constexpr int OFF_AL = 16384;
static constexpr int OFF_BH = 2 * 16384;
static constexpr int OFF_BL = 3 * 16384;
static constexpr int STAGE  = 4 * 16384;          // 64 KB per stage
static constexpr int SMEM_BYTES = 1024 /*align slack*/ + 2 * STAGE;

__global__ __launch_bounds__(NTHREADS, 1)
void grouped_gemm_mma_kernel(const int* __restrict__ glist,
                             float*     __restrict__ C) {
    extern __shared__ char dynsmem[];
    const uint32_t raw   = smem_u32(dynsmem);
    const uint32_t sbase = (raw + 1023u) & ~1023u;

    const int tid  = threadIdx.x;
    const int wid  = tid >> 5;
    const int lane = tid & 31;
    const int warp_m = wid >> 1;            // 0..3 -> 32-row slab
    const int warp_n = wid & 1;             // 0..1 -> 64-col slab
    const int row0 = blockIdx.y * BM;
    const int col0 = blockIdx.x * BN;

    // group bounds
    int gl[G];
    #pragma unroll
    for (int g = 0; g < G; g++) gl[g] = glist[g];
    auto gid_of = [&](int row) {
        int g = 0;
        #pragma unroll
        for (int i = 0; i < G; i++) if (row >= gl[i]) g = i + 1;
        return g;
    };
    const int g0 = gid_of(row0);
    const int g1 = gid_of(row0 + BM - 1);
    const int nchunks = (g1 - g0 + 1) * (K / KC);

    // per-thread cp.async coordinates: idx = tid + i*256 -> r = idx>>3 (row), q = idx&7 (16B chunk)
    // issue all 4 tiles (Ah/Al/Bh/Bl) for chunk c into stage s
    auto issue_chunk = [&](int c, int s) {
        const int g  = g0 + (c >> 3);             // K/KC == 8
        const int kt = (c & 7) * KC;
        const int glo = (g == 0) ? 0 : gl[g - 1];
        const int ghi = gl[g];
        const __nv_bfloat16* __restrict__ Ah = g_Ath + kt;
        const __nv_bfloat16* __restrict__ Al = g_Atl + kt;
        const __nv_bfloat16* __restrict__ Bh = g_Bth + ((size_t)g * N + col0) * K + kt;
        const __nv_bfloat16* __restrict__ Bl = g_Btl + ((size_t)g * N + col0) * K + kt;
        const uint32_t stb = sbase + (uint32_t)(s * STAGE);
        #pragma unroll
        for (int i = 0; i < 4; i++) {
            const int idx = tid + i * NTHREADS;   // 0..1023
            const int r = idx >> 3;               // row 0..127
            const int q = idx & 7;                // 16B chunk 0..7
            const uint32_t dsw = swz128((uint32_t)(r * 128 + q * 16));
            const int grow = row0 + r;
            const uint32_t asz = (grow >= glo && grow < ghi) ? 16u : 0u;
            cp16(stb + OFF_AH + dsw, Ah + (size_t)grow * K + q * 8, asz);
            cp16(stb + OFF_AL + dsw, Al + (size_t)grow * K + q * 8, asz);
            cp16(stb + OFF_BH + dsw, Bh + (size_t)r * K + q * 8);
            cp16(stb + OFF_BL + dsw, Bl + (size_t)r * K + q * 8);
        }
        asm volatile("cp.async.commit_group;" ::: "memory");
    };

    float acc[2][8][4];
    #pragma unroll
    for (int mt = 0; mt < 2; mt++)
        #pragma unroll
        for (int nt = 0; nt < 8; nt++)
            #pragma unroll
            for (int i = 0; i < 4; i++) acc[mt][nt][i] = 0.0f;

    // per-lane ldmatrix addressing components
    const int laneA_r = lane & 15;
    const int laneA_c = (lane >> 4) << 4;
    const int laneB_r = lane & 7;
    const int laneB_c = ((lane >> 3) & 1) << 4;

    issue_chunk(0, 0);

    int stage = 0;
    for (int c = 0; c < nchunks; ++c) {
        asm volatile("cp.async.wait_group 0;" ::: "memory");
        __syncthreads();
        // prefetch next chunk into the other stage (overlaps with compute below);
        // the barrier above also guarantees every warp is done computing on that stage
        if (c + 1 < nchunks) issue_chunk(c + 1, stage ^ 1);

        const uint32_t stb = sbase + (uint32_t)(stage * STAGE);
        #pragma unroll
        for (int ks = 0; ks < 4; ks++) {
            const int ca = ks * 32;   // byte offset of k16 sub-tile within row

            uint32_t ah[2][4], al[2][4], bh[8][2], bl[8][2];
            #pragma unroll
            for (int mt = 0; mt < 2; mt++) {
                const int r = warp_m * 32 + mt * 16 + laneA_r;
                const uint32_t cc = (uint32_t)(ca + laneA_c) ^ (uint32_t)((r & 7) << 4);
                ldsm_x4(ah[mt], stb + OFF_AH + r * 128 + cc);
            }
            #pragma unroll
            for (int nt = 0; nt < 8; nt++) {
                const int r = warp_n * 64 + nt * 8 + laneB_r;
                const uint32_t cc = (uint32_t)(ca + laneB_c) ^ (uint32_t)((r & 7) << 4);
                ldsm_x2(bh[nt], stb + OFF_BH + r * 128 + cc);
            }
            #pragma unroll
            for (int mt = 0; mt < 2; mt++)
                #pragma unroll
                for (int nt = 0; nt < 8; nt++)
                    mma16816(acc[mt][nt], ah[mt], bh[nt]);

            #pragma unroll
            for (int nt = 0; nt < 8; nt++) {
                const int r = warp_n * 64 + nt * 8 + laneB_r;
                const uint32_t cc = (uint32_t)(ca + laneB_c) ^ (uint32_t)((r & 7) << 4);
                ldsm_x2(bl[nt], stb + OFF_BL + r * 128 + cc);
            }
            #pragma unroll
            for (int mt = 0; mt < 2; mt++)
                #pragma unroll
                for (int nt = 0; nt < 8; nt++)
                    mma16816(acc[mt][nt], ah[mt], bl[nt]);

            #pragma unroll
            for (int mt = 0; mt < 2; mt++) {
                const int r = warp_m * 32 + mt * 16 + laneA_r;
                const uint32_t cc = (uint32_t)(ca + laneA_c) ^ (uint32_t)((r & 7) << 4);
                ldsm_x4(al[mt], stb + OFF_AL + r * 128 + cc);
            }
            #pragma unroll
            for (int mt = 0; mt < 2; mt++)
                #pragma unroll
                for (int nt = 0; nt < 8; nt++)
                    mma16816(acc[mt][nt], al[mt], bh[nt]);
        }
        stage ^= 1;
    }

    // ---- epilogue: direct coalesced stores ----
    const int rbase = row0 + warp_m * 32 + (lane >> 2);
    const int cbase = col0 + warp_n * 64 + 2 * (lane & 3);
    #pragma unroll
    for (int mt = 0; mt < 2; mt++) {
        #pragma unroll
        for (int nt = 0; nt < 8; nt++) {
            const int r = rbase + mt * 16;
            const int cc = cbase + nt * 8;
            *reinterpret_cast<float2*>(&C[(size_t)r * N + cc]) =
                make_float2(acc[mt][nt][0], acc[mt][nt][1]);
            *reinterpret_cast<float2*>(&C[(size_t)(r + 8) * N + cc]) =
                make_float2(acc[mt][nt][2], acc[mt][nt][3]);
        }
    }
}

// ============================ launch ============================

extern "C" void kernel_launch(void* const* d_in, const int* in_sizes, int n_in,
                              void* d_out, int out_size) {
    const float* a   = (const float*)d_in[0];   // [M_TOTAL, K]
    const float* b   = (const float*)d_in[1];   // [G, K, N]
    const int*   gls = (const int*)d_in[2];     // [G]
    float*       out = (float*)d_out;           // [M_TOTAL * N]

    // 1a) split A into bf16 hi/lo
    a_split<<<(M_TOTAL * K / 4) / 256, 256>>>(a);
    // 1b) transpose + split B
    {
        dim3 grid(N / 32, K / 32, G);
        dim3 block(32, 8);
        b_transpose_split<<<grid, block>>>(b);
    }
    // 2) pipelined grouped GEMM on HMMA
    {
        cudaFuncSetAttribute(grouped_gemm_mma_kernel,
                             cudaFuncAttributeMaxDynamicSharedMemorySize, SMEM_BYTES);
        dim3 grid(N / BN, M_TOTAL / BM);   // (4, 128)
        grouped_gemm_mma_kernel<<<grid, NTHREADS, SMEM_BYTES>>>(gls, out);
    }
}